// round 3
// baseline (speedup 1.0000x reference)
#include <cuda_runtime.h>

#define TPB   128
#define M     11
#define T     4096
#define BB    32
#define S_OUT 256          // outputs per block; thread tid does t0+tid and t0+tid+128
#define NAP   150          // AP window entries needed: tid+s, s=0..20 -> 0..147
#define NU    140          // U window entries: tid+m, m=0..10 -> 0..137

typedef unsigned long long u64;

__device__ __forceinline__ u64 fma2(u64 a, u64 b, u64 c) {
    u64 d;
    asm("fma.rn.f32x2 %0, %1, %2, %3;" : "=l"(d) : "l"(a), "l"(b), "l"(c));
    return d;
}

__global__ void __launch_bounds__(TPB)
gmp_kernel(const float2* __restrict__ x,
           const float*  __restrict__ W,
           float2* __restrict__ out)
{
    // AP[k][i] = ( |u(t0+i-20)|^(k+1) , |u(t0+i+108)|^(k+1) )
    __shared__ float2 AP[4][NAP];
    // UX[i] = ( Re u(t0+i-10), Re u(t0+i+118) ), UY likewise for Im
    __shared__ float2 UX[NU], UY[NU];
    // ws2[j] = (W[j], W[j])
    __shared__ float2 ws2[495];

    const int b   = blockIdx.y;
    const int t0  = blockIdx.x * S_OUT;
    const int tid = threadIdx.x;
    const float2* xb = x + (size_t)b * T;

    // ---- stage amplitude-power pairs ----
    for (int i = tid; i < 148; i += TPB) {
        int p1 = t0 + i - 20;          // may be negative
        int p2 = p1 + 128;             // >= 108 - 20 + ... always >= 0 when t0>=0? p2 = t0+i+108 >= 0 always
        float r1 = 0.f, i1 = 0.f;
        if (p1 >= 0) { float2 v = xb[p1]; r1 = v.x; i1 = v.y; }
        float2 v2 = xb[p2];
        float s1 = r1 * r1 + i1 * i1;
        float s2 = v2.x * v2.x + v2.y * v2.y;
        float a1 = sqrtf(s1), a2 = sqrtf(s2);
        AP[0][i] = make_float2(a1,       a2);
        AP[1][i] = make_float2(s1,       s2);
        AP[2][i] = make_float2(s1 * a1,  s2 * a2);
        AP[3][i] = make_float2(s1 * s1,  s2 * s2);
    }
    // ---- stage complex-sample pairs ----
    for (int i = tid; i < 138; i += TPB) {
        int p1 = t0 + i - 10;
        int p2 = p1 + 128;
        float r1 = 0.f, i1 = 0.f;
        if (p1 >= 0) { float2 v = xb[p1]; r1 = v.x; i1 = v.y; }
        float2 v2 = xb[p2];
        UX[i] = make_float2(r1, v2.x);
        UY[i] = make_float2(i1, v2.y);
    }
    // ---- stage duplicated weights ----
    for (int j = tid; j < 495; j += TPB) {
        float w = W[j];
        ws2[j] = make_float2(w, w);
    }
    __syncthreads();

    // coefficient accumulators, packed for both outputs: c[m] = (c_t[m], c_{t+128}[m])
    u64 c[M];
#pragma unroll
    for (int m = 0; m < M; m++) c[m] = *(const u64*)&ws2[m];

#pragma unroll
    for (int k = 0; k < 4; k++) {
        u64 win[21];
#pragma unroll
        for (int s = 0; s < 21; s++) win[s] = *(const u64*)&AP[k][tid + s];
        const float2* wk = &ws2[11 + k * 121];
#pragma unroll
        for (int l = 0; l < M; l++) {
#pragma unroll
            for (int m = 0; m < M; m++) {
                u64 w = *(const u64*)&wk[l * 11 + m];   // broadcast LDS.64
                c[m] = fma2(win[m + l], w, c[m]);
            }
        }
    }

    // epilogue: out(t) = sum_m u(t+m-10) * c_m   (complex scale by real c_m)
    u64 ar = 0ull, ai = 0ull;   // (0.f, 0.f)
#pragma unroll
    for (int m = 0; m < M; m++) {
        u64 ux = *(const u64*)&UX[tid + m];
        u64 uy = *(const u64*)&UY[tid + m];
        ar = fma2(ux, c[m], ar);
        ai = fma2(uy, c[m], ai);
    }

    float2 arf = *(float2*)&ar;
    float2 aif = *(float2*)&ai;
    float2* ob = out + (size_t)b * T + t0;
    ob[tid]       = make_float2(arf.x, aif.x);
    ob[tid + 128] = make_float2(arf.y, aif.y);
}

extern "C" void kernel_launch(void* const* d_in, const int* in_sizes, int n_in,
                              void* d_out, int out_size)
{
    const float2* x = (const float2*)d_in[0];   // (32, 4096, 2) f32
    // d_in[1] = h_0 (unused by reference)
    const float*  W = (const float*)d_in[2];    // (1, 495) f32
    float2* out = (float2*)d_out;               // (32, 4096, 2) f32

    dim3 grid(T / S_OUT, BB);                   // (16, 32) = 512 blocks
    gmp_kernel<<<grid, TPB>>>(x, W, out);
}

// round 4
// speedup vs baseline: 1.0049x; 1.0049x over previous
#include <cuda_runtime.h>

#define TPB   128
#define M     11
#define T     4096
#define BB    32
#define S_OUT 256          // outputs per block; thread tid does t0+tid and t0+tid+128
#define NAP   150          // AP window entries needed: tid+s, s=0..20 -> 0..147
#define NU    140          // U window entries: tid+m, m=0..10 -> 0..137

typedef unsigned long long u64;

__device__ __forceinline__ u64 fma2(u64 a, u64 b, u64 c) {
    u64 d;
    asm("fma.rn.f32x2 %0, %1, %2, %3;" : "=l"(d) : "l"(a), "l"(b), "l"(c));
    return d;
}

__global__ void __launch_bounds__(TPB, 3)   // allow ~170 regs: occupancy is
                                            // parallelism-limited at 3.45 blocks/SM anyway
gmp_kernel(const float2* __restrict__ x,
           const float*  __restrict__ W,
           float2* __restrict__ out)
{
    // AP[k][i] = ( |u(t0+i-20)|^(k+1) , |u(t0+i+108)|^(k+1) )
    __shared__ float2 AP[4][NAP];
    // UX[i] = ( Re u(t0+i-10), Re u(t0+i+118) ), UY likewise for Im
    __shared__ float2 UX[NU], UY[NU];
    // ws2[j] = (W[j], W[j])
    __shared__ float2 ws2[495];

    const int b   = blockIdx.y;
    const int t0  = blockIdx.x * S_OUT;
    const int tid = threadIdx.x;
    const float2* xb = x + (size_t)b * T;

    // ---- stage amplitude-power pairs ----
    for (int i = tid; i < 148; i += TPB) {
        int p1 = t0 + i - 20;          // may be negative (zero-padded region)
        int p2 = p1 + 128;             // = t0 + i + 108 >= 0 always
        float r1 = 0.f, i1 = 0.f;
        if (p1 >= 0) { float2 v = xb[p1]; r1 = v.x; i1 = v.y; }
        float2 v2 = xb[p2];
        float s1 = r1 * r1 + i1 * i1;
        float s2 = v2.x * v2.x + v2.y * v2.y;
        float a1 = sqrtf(s1), a2 = sqrtf(s2);
        AP[0][i] = make_float2(a1,       a2);
        AP[1][i] = make_float2(s1,       s2);
        AP[2][i] = make_float2(s1 * a1,  s2 * a2);
        AP[3][i] = make_float2(s1 * s1,  s2 * s2);
    }
    // ---- stage complex-sample pairs ----
    for (int i = tid; i < 138; i += TPB) {
        int p1 = t0 + i - 10;
        int p2 = p1 + 128;
        float r1 = 0.f, i1 = 0.f;
        if (p1 >= 0) { float2 v = xb[p1]; r1 = v.x; i1 = v.y; }
        float2 v2 = xb[p2];
        UX[i] = make_float2(r1, v2.x);
        UY[i] = make_float2(i1, v2.y);
    }
    // ---- stage duplicated weights ----
    for (int j = tid; j < 495; j += TPB) {
        float w = W[j];
        ws2[j] = make_float2(w, w);
    }
    __syncthreads();

    // coefficient accumulators, packed for both outputs: c[m] = (c_t[m], c_{t+128}[m])
    u64 c[M];
#pragma unroll
    for (int m = 0; m < M; m++) c[m] = *(const u64*)&ws2[m];

#pragma unroll
    for (int k = 0; k < 4; k++) {
        u64 win[21];
#pragma unroll
        for (int s = 0; s < 21; s++) win[s] = *(const u64*)&AP[k][tid + s];
        const float2* wk = &ws2[11 + k * 121];
#pragma unroll
        for (int l = 0; l < M; l++) {
#pragma unroll
            for (int m = 0; m < M; m++) {
                u64 w = *(const u64*)&wk[l * 11 + m];   // broadcast LDS.64
                c[m] = fma2(win[m + l], w, c[m]);
            }
        }
    }

    // epilogue: out(t) = sum_m u(t+m-10) * c_m   (complex sample scaled by real c_m)
    u64 ar = 0ull, ai = 0ull;   // (0.f, 0.f)
#pragma unroll
    for (int m = 0; m < M; m++) {
        u64 ux = *(const u64*)&UX[tid + m];
        u64 uy = *(const u64*)&UY[tid + m];
        ar = fma2(ux, c[m], ar);
        ai = fma2(uy, c[m], ai);
    }

    float2 arf = *(float2*)&ar;
    float2 aif = *(float2*)&ai;
    float2* ob = out + (size_t)b * T + t0;
    ob[tid]       = make_float2(arf.x, aif.x);
    ob[tid + 128] = make_float2(arf.y, aif.y);
}

extern "C" void kernel_launch(void* const* d_in, const int* in_sizes, int n_in,
                              void* d_out, int out_size)
{
    const float2* x = (const float2*)d_in[0];   // (32, 4096, 2) f32
    // d_in[1] = h_0 (unused by reference)
    const float*  W = (const float*)d_in[2];    // (1, 495) f32
    float2* out = (float2*)d_out;               // (32, 4096, 2) f32

    dim3 grid(T / S_OUT, BB);                   // (16, 32) = 512 blocks
    gmp_kernel<<<grid, TPB>>>(x, W, out);
}

// round 5
// speedup vs baseline: 1.2179x; 1.2119x over previous
#include <cuda_runtime.h>

#define TPB   128
#define R     2
#define S_OUT (TPB*R)        // 256 outputs per block
#define M     11
#define T     4096
#define BB    32
#define AW    (S_OUT + 20 + 2)   // 278

__global__ void __launch_bounds__(TPB, 3)
gmp_kernel(const float2* __restrict__ x,
           const float*  __restrict__ W,
           float2* __restrict__ out)
{
    __shared__ float  Ak[4][AW];        // amplitude powers per k
    __shared__ float2 U  [S_OUT + 12];  // complex samples window
    __shared__ __align__(16) float wsK[4][M][12];  // W1 rows padded to 12 (16B-aligned)
    __shared__ float  w0s[M];

    const int b   = blockIdx.y;
    const int t0  = blockIdx.x * S_OUT;
    const int tid = threadIdx.x;
    const float2* xb = x + (size_t)b * T;

    // ---- stage amplitude powers and samples ----
    for (int j = tid; j < S_OUT + 20; j += TPB) {
        int pos = t0 + j - 20;
        float re = 0.f, im = 0.f;
        if (pos >= 0) { float2 v = xb[pos]; re = v.x; im = v.y; }
        float a2 = re * re + im * im;
        float a  = sqrtf(a2);
        Ak[0][j] = a; Ak[1][j] = a2; Ak[2][j] = a2 * a; Ak[3][j] = a2 * a2;
        if (j >= 10) U[j - 10] = make_float2(re, im);
    }
    // ---- stage weights: W0 + padded W1 rows ----
    if (tid < M) w0s[tid] = W[tid];
    for (int j = tid; j < 484; j += TPB) {
        int k = j / 121, r = j % 121, l = r / 11, m = r % 11;
        wsK[k][l][m] = W[11 + j];
    }
    for (int j = tid; j < 44; j += TPB) wsK[j / 11][j % 11][11] = 0.f;  // pad lane
    __syncthreads();

    // Outputs t = t0 + 2*tid + {0,1}
    float c0[M], c1[M];
#pragma unroll
    for (int m = 0; m < M; m++) { float w = w0s[m]; c0[m] = w; c1[m] = w; }

#pragma unroll
    for (int k = 0; k < 4; k++) {
        float win[24];
#pragma unroll
        for (int s = 0; s < 24; s += 2) {
            float2 v = *(const float2*)&Ak[k][tid * 2 + s];
            win[s] = v.x; win[s + 1] = v.y;
        }
#pragma unroll
        for (int l = 0; l < M; l++) {
            // 3 broadcast LDS.128 cover the 11 weights of row (k,l)
            float4 wa = *(const float4*)&wsK[k][l][0];
            float4 wb = *(const float4*)&wsK[k][l][4];
            float4 wc = *(const float4*)&wsK[k][l][8];
            c0[0]  = fmaf(win[l + 0],  wa.x, c0[0]);  c1[0]  = fmaf(win[l + 1],  wa.x, c1[0]);
            c0[1]  = fmaf(win[l + 1],  wa.y, c0[1]);  c1[1]  = fmaf(win[l + 2],  wa.y, c1[1]);
            c0[2]  = fmaf(win[l + 2],  wa.z, c0[2]);  c1[2]  = fmaf(win[l + 3],  wa.z, c1[2]);
            c0[3]  = fmaf(win[l + 3],  wa.w, c0[3]);  c1[3]  = fmaf(win[l + 4],  wa.w, c1[3]);
            c0[4]  = fmaf(win[l + 4],  wb.x, c0[4]);  c1[4]  = fmaf(win[l + 5],  wb.x, c1[4]);
            c0[5]  = fmaf(win[l + 5],  wb.y, c0[5]);  c1[5]  = fmaf(win[l + 6],  wb.y, c1[5]);
            c0[6]  = fmaf(win[l + 6],  wb.z, c0[6]);  c1[6]  = fmaf(win[l + 7],  wb.z, c1[6]);
            c0[7]  = fmaf(win[l + 7],  wb.w, c0[7]);  c1[7]  = fmaf(win[l + 8],  wb.w, c1[7]);
            c0[8]  = fmaf(win[l + 8],  wc.x, c0[8]);  c1[8]  = fmaf(win[l + 9],  wc.x, c1[8]);
            c0[9]  = fmaf(win[l + 9],  wc.y, c0[9]);  c1[9]  = fmaf(win[l + 10], wc.y, c1[9]);
            c0[10] = fmaf(win[l + 10], wc.z, c0[10]); c1[10] = fmaf(win[l + 11], wc.z, c1[10]);
        }
    }

    // ---- epilogue: out(t) = sum_m u(t+m-10) * c_m ----
    float2 ur[12];
#pragma unroll
    for (int s = 0; s < 12; s += 2) {
        float4 v = *(const float4*)&U[tid * 2 + s];   // even float2 index -> 16B aligned
        ur[s]     = make_float2(v.x, v.y);
        ur[s + 1] = make_float2(v.z, v.w);
    }
    float ar0 = 0.f, ai0 = 0.f, ar1 = 0.f, ai1 = 0.f;
#pragma unroll
    for (int m = 0; m < M; m++) {
        ar0 = fmaf(ur[m].x,     c0[m], ar0);  ai0 = fmaf(ur[m].y,     c0[m], ai0);
        ar1 = fmaf(ur[m + 1].x, c1[m], ar1);  ai1 = fmaf(ur[m + 1].y, c1[m], ai1);
    }

    float4* ob = (float4*)(out + (size_t)b * T + t0) + tid;
    *ob = make_float4(ar0, ai0, ar1, ai1);
}

extern "C" void kernel_launch(void* const* d_in, const int* in_sizes, int n_in,
                              void* d_out, int out_size)
{
    const float2* x = (const float2*)d_in[0];   // (32, 4096, 2) f32
    // d_in[1] = h_0 (unused by reference)
    const float*  W = (const float*)d_in[2];    // (1, 495) f32
    float2* out = (float2*)d_out;               // (32, 4096, 2) f32

    dim3 grid(T / S_OUT, BB);                   // (16, 32) = 512 blocks
    gmp_kernel<<<grid, TPB>>>(x, W, out);
}